// round 6
// baseline (speedup 1.0000x reference)
#include <cuda.h>
#include <cuda_runtime.h>
#include <cuda_bf16.h>
#include <math.h>
#include <stdint.h>

#define B_ 64
#define L_ 256
#define D_ 128
#define N_ 8192
#define KEEP_ 64
#define HID_ 1024
#define KTOT 8320
#define BM 128
#define BN 128
#define BK 32
#define STAGES 4
#define KITER 260           // KTOT / BK
#define STG_BYTES 32768     // 4 bufs x 8KB (A_hi, A_lo, B_hi, B_lo)
#define DATA_BYTES (STAGES * STG_BYTES)
#define SMEM_ALLOC (DATA_BYTES + 1024 + 64)

__device__ __align__(1024) __nv_bfloat16 g_feat_hi[(size_t)N_ * KTOT];
__device__ __align__(1024) __nv_bfloat16 g_feat_lo[(size_t)N_ * KTOT];
__device__ __align__(1024) __nv_bfloat16 g_wt_hi[(size_t)HID_ * KTOT];
__device__ __align__(1024) __nv_bfloat16 g_wt_lo[(size_t)HID_ * KTOT];
__device__ int   g_idx[N_ * KEEP_];
__device__ float g_part2[8 * N_];
__device__ int   g_mask_mode;

// ---------------- PTX helpers ----------------
__device__ __forceinline__ uint32_t smem_to_u32(const void* p) {
    uint32_t a;
    asm("{ .reg .u64 t; cvta.to.shared.u64 t, %1; cvt.u32.u64 %0, t; }" : "=r"(a) : "l"(p));
    return a;
}
#define MBAR_INIT(a, c) asm volatile("mbarrier.init.shared.b64 [%0], %1;" :: "r"((uint32_t)(a)), "r"((uint32_t)(c)) : "memory")
#define MBAR_EXPECT(a, b) asm volatile("mbarrier.arrive.expect_tx.shared.b64 _, [%0], %1;" :: "r"((uint32_t)(a)), "r"((uint32_t)(b)) : "memory")
#define MBAR_WAIT(a, p) do { \
    uint32_t _m=(uint32_t)(a), _p=(uint32_t)(p); \
    asm volatile("{\n.reg .pred P;\nW%=:\nmbarrier.try_wait.parity.acquire.cta.shared::cta.b64 P, [%0], %1, 0x989680;\n@P bra.uni D%=;\nbra.uni W%=;\nD%=:\n}" :: "r"(_m), "r"(_p) : "memory"); \
} while(0)
#define FENCE_ASYNC() asm volatile("fence.proxy.async.shared::cta;" ::: "memory")
#define TMA_2D(dst, map, cx, cy, mbar) \
    asm volatile("cp.async.bulk.tensor.2d.shared::cta.global.tile.mbarrier::complete_tx::bytes " \
        "[%0], [%1, {%2, %3}], [%4];" \
        :: "r"((uint32_t)(dst)), "l"(map), "r"((int32_t)(cx)), "r"((int32_t)(cy)), "r"((uint32_t)(mbar)) : "memory")

__device__ __forceinline__ void ldsm4(uint32_t* r, uint32_t addr) {
    asm volatile("ldmatrix.sync.aligned.m8n8.x4.shared.b16 {%0,%1,%2,%3}, [%4];"
        : "=r"(r[0]), "=r"(r[1]), "=r"(r[2]), "=r"(r[3]) : "r"(addr));
}
__device__ __forceinline__ void mma_bf16(float* d, const uint32_t* a, const uint32_t* b) {
    asm volatile("mma.sync.aligned.m16n8k16.row.col.f32.bf16.bf16.f32 "
        "{%0,%1,%2,%3}, {%4,%5,%6,%7}, {%8,%9}, {%0,%1,%2,%3};"
        : "+f"(d[0]), "+f"(d[1]), "+f"(d[2]), "+f"(d[3])
        : "r"(a[0]), "r"(a[1]), "r"(a[2]), "r"(a[3]), "r"(b[0]), "r"(b[1]));
}
// swizzled byte offset of 16B chunk c (0..3) in a 64B row — identical to HW SW64
__device__ __forceinline__ uint32_t swz(int row, int c) {
    return (uint32_t)(row * 64 + ((c ^ ((row >> 1) & 3)) << 4));
}
__device__ __forceinline__ float gelu_exact(float x) {
    return 0.5f * x * (1.0f + erff(x * 0.7071067811865476f));
}

// ---------------- small kernels (proven) ----------------
__global__ void detect_mask_kernel(const unsigned int* __restrict__ mw) {
    if (threadIdx.x | blockIdx.x) return;
    bool i32ok = true, f32ok = true;
    for (int i = 0; i < 1024; i++) {
        unsigned w = mw[i];
        if (!(w == 0u || w == 1u)) i32ok = false;
        if (!(w == 0u || w == 0x3F800000u)) f32ok = false;
    }
    g_mask_mode = i32ok ? 1 : (f32ok ? 2 : 0);
}

__global__ void gather_idx_kernel(const void* __restrict__ maskp) {
    int gw = (blockIdx.x * blockDim.x + threadIdx.x) >> 5, lane = threadIdx.x & 31;
    if (gw >= N_) return;
    const int n = gw;
    g_idx[n * KEEP_ + lane] = -1;
    g_idx[n * KEEP_ + 32 + lane] = -1;
    __syncwarp();
    const int mode = g_mask_mode;
    const unsigned char* m8 = (const unsigned char*)maskp;
    const int* m32 = (const int*)maskp;
    const float* mf = (const float*)maskp;
    int base = 0;
    for (int g = 0; g < 8 && base < KEEP_; g++) {
        int pos = g * 32 + lane;
        bool m;
        if (mode == 1)      m = (m32[(size_t)n * L_ + pos] != 0);
        else if (mode == 2) m = (mf [(size_t)n * L_ + pos] != 0.0f);
        else                m = (m8 [(size_t)n * L_ + pos] != 0);
        unsigned bal = __ballot_sync(0xffffffffu, m);
        int slot = base + __popc(bal & ((1u << lane) - 1u));
        if (m && slot < KEEP_) g_idx[n * KEEP_ + slot] = pos;
        base += __popc(bal);
    }
}

__global__ void __launch_bounds__(256)
convert_feat_kernel(const float* __restrict__ q, const float* __restrict__ kmat,
                    const int* __restrict__ bidx) {
    int row = blockIdx.x;
    const int* idxr = g_idx + row * KEEP_;
    const float* kbase = kmat + (size_t)bidx[row] * (L_ * D_);
    size_t ro = (size_t)row * KTOT;
    for (int pos = threadIdx.x; pos < KTOT; pos += 256) {
        float v;
        if (pos < D_) v = q[(size_t)row * D_ + pos];
        else {
            int j = (pos - D_) >> 7, d = (pos - D_) & 127;
            int ix = idxr[j];
            v = (ix >= 0) ? kbase[(size_t)ix * D_ + d] : 0.0f;
        }
        __nv_bfloat16 hi = __float2bfloat16_rn(v);
        g_feat_hi[ro + pos] = hi;
        g_feat_lo[ro + pos] = __float2bfloat16_rn(v - __bfloat162float(hi));
    }
}

__global__ void __launch_bounds__(256)
convert_w1_kernel(const float* __restrict__ W1) {
    __shared__ float t[32][33];
    int k0 = blockIdx.x * 32, n0 = blockIdx.y * 32;
    int tx = threadIdx.x, ty = threadIdx.y;  // 32 x 8
#pragma unroll
    for (int i = 0; i < 4; i++)
        t[ty + i * 8][tx] = W1[(size_t)(k0 + ty + i * 8) * HID_ + n0 + tx];
    __syncthreads();
#pragma unroll
    for (int i = 0; i < 4; i++) {
        int r = ty + i * 8;
        float v = t[tx][r];
        size_t o = (size_t)(n0 + r) * KTOT + k0 + tx;
        __nv_bfloat16 hi = __float2bfloat16_rn(v);
        g_wt_hi[o] = hi;
        g_wt_lo[o] = __float2bfloat16_rn(v - __bfloat162float(hi));
    }
}

// ---------------- split-bf16 mma.sync GEMM, TMA-fed pipeline ----------------
__global__ void __launch_bounds__(256, 1)
gemm_kernel(const __grid_constant__ CUtensorMap tm_ah,
            const __grid_constant__ CUtensorMap tm_al,
            const __grid_constant__ CUtensorMap tm_bh,
            const __grid_constant__ CUtensorMap tm_bl,
            const float* __restrict__ W1, const float* __restrict__ b1,
            const float* __restrict__ W2, const int* __restrict__ count)
{
    extern __shared__ char smem[];
    const uint32_t sb = smem_to_u32(smem);
    const uint32_t db = (sb + 1023u) & ~1023u;          // data base, 1KB aligned
    const uint32_t mb = db + DATA_BYTES;                // 4 mbarriers
    const int tid = threadIdx.x, lane = tid & 31, wid = tid >> 5;
    const int wm = wid >> 2, wn = wid & 3;              // 2 x 4 warp grid
    const int m0 = blockIdx.y * BM, n0 = blockIdx.x * BN;

    if (tid == 0) {
#pragma unroll
        for (int s = 0; s < STAGES; s++) MBAR_INIT(mb + s * 8, 1);
        FENCE_ASYNC();
    }
    __syncthreads();

    if (tid == 0) {
#pragma unroll
        for (int s = 0; s < STAGES; s++) {
            uint32_t st = db + s * STG_BYTES;
            MBAR_EXPECT(mb + s * 8, STG_BYTES);
            TMA_2D(st + 0,     &tm_ah, s * BK, m0, mb + s * 8);
            TMA_2D(st + 8192,  &tm_al, s * BK, m0, mb + s * 8);
            TMA_2D(st + 16384, &tm_bh, s * BK, n0, mb + s * 8);
            TMA_2D(st + 24576, &tm_bl, s * BK, n0, mb + s * 8);
        }
    }

    float acc[4][4][4];
#pragma unroll
    for (int a = 0; a < 4; a++)
#pragma unroll
        for (int b = 0; b < 4; b++)
#pragma unroll
            for (int c = 0; c < 4; c++) acc[a][b][c] = 0.0f;

    for (int kt = 0; kt < KITER; kt++) {
        const int s = kt & 3;
        MBAR_WAIT(mb + s * 8, (kt >> 2) & 1);
        const uint32_t stg = db + s * STG_BYTES;

        // ---- load ALL fragments for both k16 halves up front ----
        uint32_t ah[2][4][4], al[2][4][4], bh[2][4][2], bl[2][4][2];
#pragma unroll
        for (int ks = 0; ks < 2; ks++) {
            const int cb = ks * 2 + (lane >> 4);
#pragma unroll
            for (int mi = 0; mi < 4; mi++) {
                int row = wm * 64 + mi * 16 + (lane & 15);
                uint32_t off = swz(row, cb);
                ldsm4(ah[ks][mi], stg + 0    + off);
                ldsm4(al[ks][mi], stg + 8192 + off);
            }
#pragma unroll
            for (int nj = 0; nj < 2; nj++) {
                int row = wn * 32 + nj * 16 + (lane & 15);
                uint32_t off = swz(row, cb);
                uint32_t t[4];
                ldsm4(t, stg + 16384 + off);
                bh[ks][nj*2][0] = t[0]; bh[ks][nj*2][1] = t[2];
                bh[ks][nj*2+1][0] = t[1]; bh[ks][nj*2+1][1] = t[3];
                ldsm4(t, stg + 24576 + off);
                bl[ks][nj*2][0] = t[0]; bl[ks][nj*2][1] = t[2];
                bl[ks][nj*2+1][0] = t[1]; bl[ks][nj*2+1][1] = t[3];
            }
        }

        // stage consumed (all data in registers) -> allow refill to overlap mma
        __syncthreads();
        if (tid == 0 && kt + STAGES < KITER) {
            int kn = kt + STAGES;
            uint32_t st = db + s * STG_BYTES;
            MBAR_EXPECT(mb + s * 8, STG_BYTES);
            TMA_2D(st + 0,     &tm_ah, kn * BK, m0, mb + s * 8);
            TMA_2D(st + 8192,  &tm_al, kn * BK, m0, mb + s * 8);
            TMA_2D(st + 16384, &tm_bh, kn * BK, n0, mb + s * 8);
            TMA_2D(st + 24576, &tm_bl, kn * BK, n0, mb + s * 8);
        }

        // ---- 96 back-to-back HMMA, no load dependencies ----
#pragma unroll
        for (int ks = 0; ks < 2; ks++)
#pragma unroll
            for (int mi = 0; mi < 4; mi++)
#pragma unroll
                for (int ni = 0; ni < 4; ni++) {
                    mma_bf16(acc[mi][ni], ah[ks][mi], bh[ks][ni]);
                    mma_bf16(acc[mi][ni], ah[ks][mi], bl[ks][ni]);
                    mma_bf16(acc[mi][ni], al[ks][mi], bh[ks][ni]);
                }
    }

    // ---- fused epilogue: z = acc + b1 + lc*W1[8320]; gelu(z)*W2 row-reduce ----
    const int r = lane >> 2, c2 = (lane & 3) * 2;
    const float* wl = W1 + (size_t)8320 * HID_;
    float pA[4], pB[4], lcA[4], lcB[4];
#pragma unroll
    for (int mi = 0; mi < 4; mi++) {
        int rowA = m0 + wm * 64 + mi * 16 + r;
        lcA[mi] = log1pf((float)count[rowA]);
        lcB[mi] = log1pf((float)count[rowA + 8]);
        pA[mi] = 0.0f; pB[mi] = 0.0f;
    }
#pragma unroll
    for (int ni = 0; ni < 4; ni++) {
        int n = n0 + wn * 32 + ni * 8 + c2;
        float b10 = b1[n], b11 = b1[n + 1];
        float wl0 = wl[n], wl1 = wl[n + 1];
        float w20 = W2[n], w21 = W2[n + 1];
#pragma unroll
        for (int mi = 0; mi < 4; mi++) {
            pA[mi] += gelu_exact(acc[mi][ni][0] + b10 + lcA[mi] * wl0) * w20
                    + gelu_exact(acc[mi][ni][1] + b11 + lcA[mi] * wl1) * w21;
            pB[mi] += gelu_exact(acc[mi][ni][2] + b10 + lcB[mi] * wl0) * w20
                    + gelu_exact(acc[mi][ni][3] + b11 + lcB[mi] * wl1) * w21;
        }
    }
#pragma unroll
    for (int mi = 0; mi < 4; mi++) {
        pA[mi] += __shfl_xor_sync(0xffffffffu, pA[mi], 1);
        pA[mi] += __shfl_xor_sync(0xffffffffu, pA[mi], 2);
        pB[mi] += __shfl_xor_sync(0xffffffffu, pB[mi], 1);
        pB[mi] += __shfl_xor_sync(0xffffffffu, pB[mi], 2);
    }
    __syncthreads();
    float* red = (float*)smem;          // reuse pipeline smem: [128 rows][4 wn]
    if ((lane & 3) == 0) {
#pragma unroll
        for (int mi = 0; mi < 4; mi++) {
            int rA = wm * 64 + mi * 16 + r;
            red[rA * 4 + wn]       = pA[mi];
            red[(rA + 8) * 4 + wn] = pB[mi];
        }
    }
    __syncthreads();
    if (tid < 128) {
        float s = red[tid*4] + red[tid*4+1] + red[tid*4+2] + red[tid*4+3];
        g_part2[(size_t)blockIdx.x * N_ + m0 + tid] = s;
    }
}

__global__ void final_kernel(const float* __restrict__ b2, float* __restrict__ out) {
    int i = blockIdx.x * 256 + threadIdx.x;
    float s = b2[0];
#pragma unroll
    for (int nb = 0; nb < 8; nb++) s += g_part2[(size_t)nb * N_ + i];
    out[i] = s;
}

// ---------------- host ----------------
typedef CUresult (CUDAAPI *EncodeFn)(
    CUtensorMap*, CUtensorMapDataType, cuuint32_t, void*,
    const cuuint64_t*, const cuuint64_t*, const cuuint32_t*, const cuuint32_t*,
    CUtensorMapInterleave, CUtensorMapSwizzle, CUtensorMapL2promotion, CUtensorMapFloatOOBfill);

static void encode2d(EncodeFn enc, CUtensorMap* m, void* ptr, uint64_t d0, uint64_t d1) {
    cuuint64_t dims[2] = {d0, d1};
    cuuint64_t strides[1] = {d0 * 2};
    cuuint32_t box[2] = {32u, 128u};   // 64B x 128 rows
    cuuint32_t es[2] = {1u, 1u};
    enc(m, CU_TENSOR_MAP_DATA_TYPE_BFLOAT16, 2, ptr, dims, strides, box, es,
        CU_TENSOR_MAP_INTERLEAVE_NONE, CU_TENSOR_MAP_SWIZZLE_64B,
        CU_TENSOR_MAP_L2_PROMOTION_L2_128B, CU_TENSOR_MAP_FLOAT_OOB_FILL_NONE);
}

extern "C" void kernel_launch(void* const* d_in, const int* in_sizes, int n_in,
                              void* d_out, int out_size) {
    const float* q     = (const float*)d_in[0];
    const float* k     = (const float*)d_in[1];
    const int*   bidx  = (const int*)d_in[2];
    const void*  mask  = d_in[3];
    const int*   count = (const int*)d_in[4];
    const float* W1    = (const float*)d_in[5];
    const float* b1    = (const float*)d_in[6];
    const float* W2    = (const float*)d_in[7];
    const float* b2    = (const float*)d_in[8];
    float* out = (float*)d_out;

    void* encp = nullptr;
    cudaDriverEntryPointQueryResult st;
    cudaGetDriverEntryPointByVersion("cuTensorMapEncodeTiled", &encp, 12000,
                                     cudaEnableDefault, &st);
    EncodeFn enc = (EncodeFn)encp;

    void *p_fh, *p_fl, *p_wh, *p_wl;
    cudaGetSymbolAddress(&p_fh, g_feat_hi);
    cudaGetSymbolAddress(&p_fl, g_feat_lo);
    cudaGetSymbolAddress(&p_wh, g_wt_hi);
    cudaGetSymbolAddress(&p_wl, g_wt_lo);

    CUtensorMap tm_ah, tm_al, tm_bh, tm_bl;
    encode2d(enc, &tm_ah, p_fh, KTOT, N_);
    encode2d(enc, &tm_al, p_fl, KTOT, N_);
    encode2d(enc, &tm_bh, p_wh, KTOT, HID_);
    encode2d(enc, &tm_bl, p_wl, KTOT, HID_);

    cudaFuncSetAttribute(gemm_kernel, cudaFuncAttributeMaxDynamicSharedMemorySize, SMEM_ALLOC);

    detect_mask_kernel<<<1, 32>>>((const unsigned int*)mask);
    gather_idx_kernel<<<N_ / 8, 256>>>(mask);
    convert_feat_kernel<<<N_, 256>>>(q, k, bidx);
    convert_w1_kernel<<<dim3(KTOT / 32, HID_ / 32), dim3(32, 8)>>>(W1);
    gemm_kernel<<<dim3(HID_ / BN, N_ / BM), 256, SMEM_ALLOC>>>(tm_ah, tm_al, tm_bh, tm_bl,
                                                               W1, b1, W2, count);
    final_kernel<<<N_ / 256, 256>>>(b2, out);
}

// round 7
// speedup vs baseline: 1.2203x; 1.2203x over previous
#include <cuda.h>
#include <cuda_runtime.h>
#include <cuda_bf16.h>
#include <math.h>
#include <stdint.h>

#define B_ 64
#define L_ 256
#define D_ 128
#define N_ 8192
#define KEEP_ 64
#define HID_ 1024
#define KTOT 8320
#define BM 128
#define BN 128
#define BK 64
#define STAGES 3
#define KITER 130           // KTOT / BK
#define STG_BYTES 65536     // 4 bufs x 16KB (A_hi, A_lo, B_hi, B_lo)
#define DATA_BYTES (STAGES * STG_BYTES)
#define SMEM_ALLOC (DATA_BYTES + 1024 + 64)

__device__ __align__(1024) __nv_bfloat16 g_feat_hi[(size_t)N_ * KTOT];
__device__ __align__(1024) __nv_bfloat16 g_feat_lo[(size_t)N_ * KTOT];
__device__ __align__(1024) __nv_bfloat16 g_wt_hi[(size_t)HID_ * KTOT];
__device__ __align__(1024) __nv_bfloat16 g_wt_lo[(size_t)HID_ * KTOT];
__device__ int   g_idx[N_ * KEEP_];
__device__ float g_part2[8 * N_];
__device__ int   g_mask_mode;

// ---------------- PTX helpers ----------------
__device__ __forceinline__ uint32_t smem_to_u32(const void* p) {
    uint32_t a;
    asm("{ .reg .u64 t; cvta.to.shared.u64 t, %1; cvt.u32.u64 %0, t; }" : "=r"(a) : "l"(p));
    return a;
}
#define MBAR_INIT(a, c) asm volatile("mbarrier.init.shared.b64 [%0], %1;" :: "r"((uint32_t)(a)), "r"((uint32_t)(c)) : "memory")
#define MBAR_EXPECT(a, b) asm volatile("mbarrier.arrive.expect_tx.shared.b64 _, [%0], %1;" :: "r"((uint32_t)(a)), "r"((uint32_t)(b)) : "memory")
#define MBAR_WAIT(a, p) do { \
    uint32_t _m=(uint32_t)(a), _p=(uint32_t)(p); \
    asm volatile("{\n.reg .pred P;\nW%=:\nmbarrier.try_wait.parity.acquire.cta.shared::cta.b64 P, [%0], %1, 0x989680;\n@P bra.uni D%=;\nbra.uni W%=;\nD%=:\n}" :: "r"(_m), "r"(_p) : "memory"); \
} while(0)
#define FENCE_ASYNC() asm volatile("fence.proxy.async.shared::cta;" ::: "memory")
#define TMA_2D(dst, map, cx, cy, mbar) \
    asm volatile("cp.async.bulk.tensor.2d.shared::cta.global.tile.mbarrier::complete_tx::bytes " \
        "[%0], [%1, {%2, %3}], [%4];" \
        :: "r"((uint32_t)(dst)), "l"(map), "r"((int32_t)(cx)), "r"((int32_t)(cy)), "r"((uint32_t)(mbar)) : "memory")

__device__ __forceinline__ void ldsm4(uint32_t* r, uint32_t addr) {
    asm volatile("ldmatrix.sync.aligned.m8n8.x4.shared.b16 {%0,%1,%2,%3}, [%4];"
        : "=r"(r[0]), "=r"(r[1]), "=r"(r[2]), "=r"(r[3]) : "r"(addr));
}
__device__ __forceinline__ void mma_bf16(float* d, const uint32_t* a, const uint32_t* b) {
    asm volatile("mma.sync.aligned.m16n8k16.row.col.f32.bf16.bf16.f32 "
        "{%0,%1,%2,%3}, {%4,%5,%6,%7}, {%8,%9}, {%0,%1,%2,%3};"
        : "+f"(d[0]), "+f"(d[1]), "+f"(d[2]), "+f"(d[3])
        : "r"(a[0]), "r"(a[1]), "r"(a[2]), "r"(a[3]), "r"(b[0]), "r"(b[1]));
}
// SW128: 16B chunk c (0..7) in a 128B row, tile 1KB-aligned -> c ^= (row & 7)
__device__ __forceinline__ uint32_t swz(int row, int c) {
    return (uint32_t)(row * 128 + ((c ^ (row & 7)) << 4));
}
__device__ __forceinline__ float gelu_exact(float x) {
    return 0.5f * x * (1.0f + erff(x * 0.7071067811865476f));
}

// ---------------- small kernels (proven) ----------------
__global__ void detect_mask_kernel(const unsigned int* __restrict__ mw) {
    if (threadIdx.x | blockIdx.x) return;
    bool i32ok = true, f32ok = true;
    for (int i = 0; i < 1024; i++) {
        unsigned w = mw[i];
        if (!(w == 0u || w == 1u)) i32ok = false;
        if (!(w == 0u || w == 0x3F800000u)) f32ok = false;
    }
    g_mask_mode = i32ok ? 1 : (f32ok ? 2 : 0);
}

__global__ void gather_idx_kernel(const void* __restrict__ maskp) {
    int gw = (blockIdx.x * blockDim.x + threadIdx.x) >> 5, lane = threadIdx.x & 31;
    if (gw >= N_) return;
    const int n = gw;
    g_idx[n * KEEP_ + lane] = -1;
    g_idx[n * KEEP_ + 32 + lane] = -1;
    __syncwarp();
    const int mode = g_mask_mode;
    const unsigned char* m8 = (const unsigned char*)maskp;
    const int* m32 = (const int*)maskp;
    const float* mf = (const float*)maskp;
    int base = 0;
    for (int g = 0; g < 8 && base < KEEP_; g++) {
        int pos = g * 32 + lane;
        bool m;
        if (mode == 1)      m = (m32[(size_t)n * L_ + pos] != 0);
        else if (mode == 2) m = (mf [(size_t)n * L_ + pos] != 0.0f);
        else                m = (m8 [(size_t)n * L_ + pos] != 0);
        unsigned bal = __ballot_sync(0xffffffffu, m);
        int slot = base + __popc(bal & ((1u << lane) - 1u));
        if (m && slot < KEEP_) g_idx[n * KEEP_ + slot] = pos;
        base += __popc(bal);
    }
}

__global__ void __launch_bounds__(256)
convert_feat_kernel(const float* __restrict__ q, const float* __restrict__ kmat,
                    const int* __restrict__ bidx) {
    int row = blockIdx.x;
    const int* idxr = g_idx + row * KEEP_;
    const float* kbase = kmat + (size_t)bidx[row] * (L_ * D_);
    size_t ro = (size_t)row * KTOT;
    for (int pos = threadIdx.x; pos < KTOT; pos += 256) {
        float v;
        if (pos < D_) v = q[(size_t)row * D_ + pos];
        else {
            int j = (pos - D_) >> 7, d = (pos - D_) & 127;
            int ix = idxr[j];
            v = (ix >= 0) ? kbase[(size_t)ix * D_ + d] : 0.0f;
        }
        __nv_bfloat16 hi = __float2bfloat16_rn(v);
        g_feat_hi[ro + pos] = hi;
        g_feat_lo[ro + pos] = __float2bfloat16_rn(v - __bfloat162float(hi));
    }
}

__global__ void __launch_bounds__(256)
convert_w1_kernel(const float* __restrict__ W1) {
    __shared__ float t[32][33];
    int k0 = blockIdx.x * 32, n0 = blockIdx.y * 32;
    int tx = threadIdx.x, ty = threadIdx.y;  // 32 x 8
#pragma unroll
    for (int i = 0; i < 4; i++)
        t[ty + i * 8][tx] = W1[(size_t)(k0 + ty + i * 8) * HID_ + n0 + tx];
    __syncthreads();
#pragma unroll
    for (int i = 0; i < 4; i++) {
        int r = ty + i * 8;
        float v = t[tx][r];
        size_t o = (size_t)(n0 + r) * KTOT + k0 + tx;
        __nv_bfloat16 hi = __float2bfloat16_rn(v);
        g_wt_hi[o] = hi;
        g_wt_lo[o] = __float2bfloat16_rn(v - __bfloat162float(hi));
    }
}

// ---------------- split-bf16 mma.sync GEMM, TMA-fed pipeline ----------------
__global__ void __launch_bounds__(256, 1)
gemm_kernel(const __grid_constant__ CUtensorMap tm_ah,
            const __grid_constant__ CUtensorMap tm_al,
            const __grid_constant__ CUtensorMap tm_bh,
            const __grid_constant__ CUtensorMap tm_bl,
            const float* __restrict__ W1, const float* __restrict__ b1,
            const float* __restrict__ W2, const int* __restrict__ count)
{
    extern __shared__ char smem[];
    const uint32_t sb = smem_to_u32(smem);
    const uint32_t db = (sb + 1023u) & ~1023u;          // data base, 1KB aligned
    const uint32_t mb = db + DATA_BYTES;                // 3 mbarriers
    const int tid = threadIdx.x, lane = tid & 31, wid = tid >> 5;
    const int wm = wid >> 2, wn = wid & 3;              // 2 x 4 warp grid
    const int m0 = blockIdx.y * BM, n0 = blockIdx.x * BN;

    if (tid == 0) {
#pragma unroll
        for (int s = 0; s < STAGES; s++) MBAR_INIT(mb + s * 8, 1);
        FENCE_ASYNC();
    }
    __syncthreads();

    if (tid == 0) {
#pragma unroll
        for (int s = 0; s < STAGES; s++) {
            uint32_t st = db + s * STG_BYTES;
            MBAR_EXPECT(mb + s * 8, STG_BYTES);
            TMA_2D(st + 0,     &tm_ah, s * BK, m0, mb + s * 8);
            TMA_2D(st + 16384, &tm_al, s * BK, m0, mb + s * 8);
            TMA_2D(st + 32768, &tm_bh, s * BK, n0, mb + s * 8);
            TMA_2D(st + 49152, &tm_bl, s * BK, n0, mb + s * 8);
        }
    }

    float acc[4][4][4];
#pragma unroll
    for (int a = 0; a < 4; a++)
#pragma unroll
        for (int b = 0; b < 4; b++)
#pragma unroll
            for (int c = 0; c < 4; c++) acc[a][b][c] = 0.0f;

    int s = 0, phase = 0;
    for (int kt = 0; kt < KITER; kt++) {
        MBAR_WAIT(mb + s * 8, phase);
        const uint32_t stg = db + s * STG_BYTES;

#pragma unroll
        for (int ks = 0; ks < 4; ks++) {
            uint32_t ah[4][4], al[4][4], bh[4][2], bl[4][2];
            const int cb = ks * 2 + (lane >> 4);
#pragma unroll
            for (int mi = 0; mi < 4; mi++) {
                int row = wm * 64 + mi * 16 + (lane & 15);
                uint32_t off = swz(row, cb);
                ldsm4(ah[mi], stg + 0     + off);
                ldsm4(al[mi], stg + 16384 + off);
            }
#pragma unroll
            for (int nj = 0; nj < 2; nj++) {
                int row = wn * 32 + nj * 16 + (lane & 15);
                uint32_t off = swz(row, cb);
                uint32_t t[4];
                ldsm4(t, stg + 32768 + off);
                bh[nj*2][0] = t[0]; bh[nj*2][1] = t[2];
                bh[nj*2+1][0] = t[1]; bh[nj*2+1][1] = t[3];
                ldsm4(t, stg + 49152 + off);
                bl[nj*2][0] = t[0]; bl[nj*2][1] = t[2];
                bl[nj*2+1][0] = t[1]; bl[nj*2+1][1] = t[3];
            }

            if (ks == 3) {
                // all LDSM reads of this stage are done -> refill overlaps mma
                __syncthreads();
                if (tid == 0 && kt + STAGES < KITER) {
                    int kn = kt + STAGES;
                    uint32_t st = db + s * STG_BYTES;
                    MBAR_EXPECT(mb + s * 8, STG_BYTES);
                    TMA_2D(st + 0,     &tm_ah, kn * BK, m0, mb + s * 8);
                    TMA_2D(st + 16384, &tm_al, kn * BK, m0, mb + s * 8);
                    TMA_2D(st + 32768, &tm_bh, kn * BK, n0, mb + s * 8);
                    TMA_2D(st + 49152, &tm_bl, kn * BK, n0, mb + s * 8);
                }
            }
#pragma unroll
            for (int mi = 0; mi < 4; mi++)
#pragma unroll
                for (int ni = 0; ni < 4; ni++) {
                    mma_bf16(acc[mi][ni], ah[mi], bh[ni]);
                    mma_bf16(acc[mi][ni], ah[mi], bl[ni]);
                    mma_bf16(acc[mi][ni], al[mi], bh[ni]);
                }
        }
        if (++s == STAGES) { s = 0; phase ^= 1; }
    }

    // ---- fused epilogue: z = acc + b1 + lc*W1[8320]; gelu(z)*W2 row-reduce ----
    const int r = lane >> 2, c2 = (lane & 3) * 2;
    const float* wl = W1 + (size_t)8320 * HID_;
    float pA[4], pB[4], lcA[4], lcB[4];
#pragma unroll
    for (int mi = 0; mi < 4; mi++) {
        int rowA = m0 + wm * 64 + mi * 16 + r;
        lcA[mi] = log1pf((float)count[rowA]);
        lcB[mi] = log1pf((float)count[rowA + 8]);
        pA[mi] = 0.0f; pB[mi] = 0.0f;
    }
#pragma unroll
    for (int ni = 0; ni < 4; ni++) {
        int n = n0 + wn * 32 + ni * 8 + c2;
        float b10 = b1[n], b11 = b1[n + 1];
        float wl0 = wl[n], wl1 = wl[n + 1];
        float w20 = W2[n], w21 = W2[n + 1];
#pragma unroll
        for (int mi = 0; mi < 4; mi++) {
            pA[mi] += gelu_exact(acc[mi][ni][0] + b10 + lcA[mi] * wl0) * w20
                    + gelu_exact(acc[mi][ni][1] + b11 + lcA[mi] * wl1) * w21;
            pB[mi] += gelu_exact(acc[mi][ni][2] + b10 + lcB[mi] * wl0) * w20
                    + gelu_exact(acc[mi][ni][3] + b11 + lcB[mi] * wl1) * w21;
        }
    }
#pragma unroll
    for (int mi = 0; mi < 4; mi++) {
        pA[mi] += __shfl_xor_sync(0xffffffffu, pA[mi], 1);
        pA[mi] += __shfl_xor_sync(0xffffffffu, pA[mi], 2);
        pB[mi] += __shfl_xor_sync(0xffffffffu, pB[mi], 1);
        pB[mi] += __shfl_xor_sync(0xffffffffu, pB[mi], 2);
    }
    __syncthreads();
    float* red = (float*)smem;          // reuse pipeline smem: [128 rows][4 wn]
    if ((lane & 3) == 0) {
#pragma unroll
        for (int mi = 0; mi < 4; mi++) {
            int rA = wm * 64 + mi * 16 + r;
            red[rA * 4 + wn]       = pA[mi];
            red[(rA + 8) * 4 + wn] = pB[mi];
        }
    }
    __syncthreads();
    if (tid < 128) {
        float sum = red[tid*4] + red[tid*4+1] + red[tid*4+2] + red[tid*4+3];
        g_part2[(size_t)blockIdx.x * N_ + m0 + tid] = sum;
    }
}

__global__ void final_kernel(const float* __restrict__ b2, float* __restrict__ out) {
    int i = blockIdx.x * 256 + threadIdx.x;
    float s = b2[0];
#pragma unroll
    for (int nb = 0; nb < 8; nb++) s += g_part2[(size_t)nb * N_ + i];
    out[i] = s;
}

// ---------------- host ----------------
typedef CUresult (CUDAAPI *EncodeFn)(
    CUtensorMap*, CUtensorMapDataType, cuuint32_t, void*,
    const cuuint64_t*, const cuuint64_t*, const cuuint32_t*, const cuuint32_t*,
    CUtensorMapInterleave, CUtensorMapSwizzle, CUtensorMapL2promotion, CUtensorMapFloatOOBfill);

static void encode2d(EncodeFn enc, CUtensorMap* m, void* ptr, uint64_t d0, uint64_t d1) {
    cuuint64_t dims[2] = {d0, d1};
    cuuint64_t strides[1] = {d0 * 2};
    cuuint32_t box[2] = {64u, 128u};   // 128B x 128 rows, SW128
    cuuint32_t es[2] = {1u, 1u};
    enc(m, CU_TENSOR_MAP_DATA_TYPE_BFLOAT16, 2, ptr, dims, strides, box, es,
        CU_TENSOR_MAP_INTERLEAVE_NONE, CU_TENSOR_MAP_SWIZZLE_128B,
        CU_TENSOR_MAP_L2_PROMOTION_L2_128B, CU_TENSOR_MAP_FLOAT_OOB_FILL_NONE);
}

extern "C" void kernel_launch(void* const* d_in, const int* in_sizes, int n_in,
                              void* d_out, int out_size) {
    const float* q     = (const float*)d_in[0];
    const float* k     = (const float*)d_in[1];
    const int*   bidx  = (const int*)d_in[2];
    const void*  mask  = d_in[3];
    const int*   count = (const int*)d_in[4];
    const float* W1    = (const float*)d_in[5];
    const float* b1    = (const float*)d_in[6];
    const float* W2    = (const float*)d_in[7];
    const float* b2    = (const float*)d_in[8];
    float* out = (float*)d_out;

    void* encp = nullptr;
    cudaDriverEntryPointQueryResult st;
    cudaGetDriverEntryPointByVersion("cuTensorMapEncodeTiled", &encp, 12000,
                                     cudaEnableDefault, &st);
    EncodeFn enc = (EncodeFn)encp;

    void *p_fh, *p_fl, *p_wh, *p_wl;
    cudaGetSymbolAddress(&p_fh, g_feat_hi);
    cudaGetSymbolAddress(&p_fl, g_feat_lo);
    cudaGetSymbolAddress(&p_wh, g_wt_hi);
    cudaGetSymbolAddress(&p_wl, g_wt_lo);

    CUtensorMap tm_ah, tm_al, tm_bh, tm_bl;
    encode2d(enc, &tm_ah, p_fh, KTOT, N_);
    encode2d(enc, &tm_al, p_fl, KTOT, N_);
    encode2d(enc, &tm_bh, p_wh, KTOT, HID_);
    encode2d(enc, &tm_bl, p_wl, KTOT, HID_);

    cudaFuncSetAttribute(gemm_kernel, cudaFuncAttributeMaxDynamicSharedMemorySize, SMEM_ALLOC);

    detect_mask_kernel<<<1, 32>>>((const unsigned int*)mask);
    gather_idx_kernel<<<N_ / 8, 256>>>(mask);
    convert_feat_kernel<<<N_, 256>>>(q, k, bidx);
    convert_w1_kernel<<<dim3(KTOT / 32, HID_ / 32), dim3(32, 8)>>>(W1);
    gemm_kernel<<<dim3(HID_ / BN, N_ / BM), 256, SMEM_ALLOC>>>(tm_ah, tm_al, tm_bh, tm_bl,
                                                               W1, b1, W2, count);
    final_kernel<<<N_ / 256, 256>>>(b2, out);
}

// round 8
// speedup vs baseline: 1.2727x; 1.0430x over previous
#include <cuda.h>
#include <cuda_runtime.h>
#include <cuda_bf16.h>
#include <math.h>
#include <stdint.h>

#define B_ 64
#define L_ 256
#define D_ 128
#define N_ 8192
#define KEEP_ 64
#define HID_ 1024
#define KTOT 8320
#define BM 256
#define BN 128
#define BK 64
#define STAGES 2
#define KITER 130           // KTOT / BK
// stage: A_hi 32KB, A_lo 32KB, B_hi 16KB, B_lo 16KB
#define STG_BYTES 98304
#define A_HI 0
#define A_LO 32768
#define B_HI 65536
#define B_LO 81920
#define DATA_BYTES (STAGES * STG_BYTES)
#define SMEM_ALLOC (DATA_BYTES + 1024 + 64)

__device__ __align__(1024) __nv_bfloat16 g_feat_hi[(size_t)N_ * KTOT];
__device__ __align__(1024) __nv_bfloat16 g_feat_lo[(size_t)N_ * KTOT];
__device__ __align__(1024) __nv_bfloat16 g_wt_hi[(size_t)HID_ * KTOT];
__device__ __align__(1024) __nv_bfloat16 g_wt_lo[(size_t)HID_ * KTOT];
__device__ int   g_idx[N_ * KEEP_];
__device__ float g_part2[8 * N_];
__device__ int   g_mask_mode;

// ---------------- PTX helpers ----------------
__device__ __forceinline__ uint32_t smem_to_u32(const void* p) {
    uint32_t a;
    asm("{ .reg .u64 t; cvta.to.shared.u64 t, %1; cvt.u32.u64 %0, t; }" : "=r"(a) : "l"(p));
    return a;
}
#define MBAR_INIT(a, c) asm volatile("mbarrier.init.shared.b64 [%0], %1;" :: "r"((uint32_t)(a)), "r"((uint32_t)(c)) : "memory")
#define MBAR_EXPECT(a, b) asm volatile("mbarrier.arrive.expect_tx.shared.b64 _, [%0], %1;" :: "r"((uint32_t)(a)), "r"((uint32_t)(b)) : "memory")
#define MBAR_WAIT(a, p) do { \
    uint32_t _m=(uint32_t)(a), _p=(uint32_t)(p); \
    asm volatile("{\n.reg .pred P;\nW%=:\nmbarrier.try_wait.parity.acquire.cta.shared::cta.b64 P, [%0], %1, 0x989680;\n@P bra.uni D%=;\nbra.uni W%=;\nD%=:\n}" :: "r"(_m), "r"(_p) : "memory"); \
} while(0)
#define FENCE_ASYNC() asm volatile("fence.proxy.async.shared::cta;" ::: "memory")
#define TMA_2D(dst, map, cx, cy, mbar) \
    asm volatile("cp.async.bulk.tensor.2d.shared::cta.global.tile.mbarrier::complete_tx::bytes " \
        "[%0], [%1, {%2, %3}], [%4];" \
        :: "r"((uint32_t)(dst)), "l"(map), "r"((int32_t)(cx)), "r"((int32_t)(cy)), "r"((uint32_t)(mbar)) : "memory")

__device__ __forceinline__ void ldsm4(uint32_t* r, uint32_t addr) {
    asm volatile("ldmatrix.sync.aligned.m8n8.x4.shared.b16 {%0,%1,%2,%3}, [%4];"
        : "=r"(r[0]), "=r"(r[1]), "=r"(r[2]), "=r"(r[3]) : "r"(addr));
}
__device__ __forceinline__ void mma_bf16(float* d, const uint32_t* a, const uint32_t* b) {
    asm volatile("mma.sync.aligned.m16n8k16.row.col.f32.bf16.bf16.f32 "
        "{%0,%1,%2,%3}, {%4,%5,%6,%7}, {%8,%9}, {%0,%1,%2,%3};"
        : "+f"(d[0]), "+f"(d[1]), "+f"(d[2]), "+f"(d[3])
        : "r"(a[0]), "r"(a[1]), "r"(a[2]), "r"(a[3]), "r"(b[0]), "r"(b[1]));
}
// SW128: 16B chunk c (0..7) in a 128B row, tile 1KB-aligned -> c ^= (row & 7)
__device__ __forceinline__ uint32_t swz(int row, int c) {
    return (uint32_t)(row * 128 + ((c ^ (row & 7)) << 4));
}
__device__ __forceinline__ float gelu_exact(float x) {
    return 0.5f * x * (1.0f + erff(x * 0.7071067811865476f));
}

// ---------------- small kernels (proven) ----------------
__global__ void detect_mask_kernel(const unsigned int* __restrict__ mw) {
    if (threadIdx.x | blockIdx.x) return;
    bool i32ok = true, f32ok = true;
    for (int i = 0; i < 1024; i++) {
        unsigned w = mw[i];
        if (!(w == 0u || w == 1u)) i32ok = false;
        if (!(w == 0u || w == 0x3F800000u)) f32ok = false;
    }
    g_mask_mode = i32ok ? 1 : (f32ok ? 2 : 0);
}

__global__ void gather_idx_kernel(const void* __restrict__ maskp) {
    int gw = (blockIdx.x * blockDim.x + threadIdx.x) >> 5, lane = threadIdx.x & 31;
    if (gw >= N_) return;
    const int n = gw;
    g_idx[n * KEEP_ + lane] = -1;
    g_idx[n * KEEP_ + 32 + lane] = -1;
    __syncwarp();
    const int mode = g_mask_mode;
    const unsigned char* m8 = (const unsigned char*)maskp;
    const int* m32 = (const int*)maskp;
    const float* mf = (const float*)maskp;
    int base = 0;
    for (int g = 0; g < 8 && base < KEEP_; g++) {
        int pos = g * 32 + lane;
        bool m;
        if (mode == 1)      m = (m32[(size_t)n * L_ + pos] != 0);
        else if (mode == 2) m = (mf [(size_t)n * L_ + pos] != 0.0f);
        else                m = (m8 [(size_t)n * L_ + pos] != 0);
        unsigned bal = __ballot_sync(0xffffffffu, m);
        int slot = base + __popc(bal & ((1u << lane) - 1u));
        if (m && slot < KEEP_) g_idx[n * KEEP_ + slot] = pos;
        base += __popc(bal);
    }
}

__global__ void __launch_bounds__(256)
convert_feat_kernel(const float* __restrict__ q, const float* __restrict__ kmat,
                    const int* __restrict__ bidx) {
    int row = blockIdx.x;
    const int* idxr = g_idx + row * KEEP_;
    const float* kbase = kmat + (size_t)bidx[row] * (L_ * D_);
    size_t ro = (size_t)row * KTOT;
    for (int pos = threadIdx.x; pos < KTOT; pos += 256) {
        float v;
        if (pos < D_) v = q[(size_t)row * D_ + pos];
        else {
            int j = (pos - D_) >> 7, d = (pos - D_) & 127;
            int ix = idxr[j];
            v = (ix >= 0) ? kbase[(size_t)ix * D_ + d] : 0.0f;
        }
        __nv_bfloat16 hi = __float2bfloat16_rn(v);
        g_feat_hi[ro + pos] = hi;
        g_feat_lo[ro + pos] = __float2bfloat16_rn(v - __bfloat162float(hi));
    }
}

__global__ void __launch_bounds__(256)
convert_w1_kernel(const float* __restrict__ W1) {
    __shared__ float t[32][33];
    int k0 = blockIdx.x * 32, n0 = blockIdx.y * 32;
    int tx = threadIdx.x, ty = threadIdx.y;  // 32 x 8
#pragma unroll
    for (int i = 0; i < 4; i++)
        t[ty + i * 8][tx] = W1[(size_t)(k0 + ty + i * 8) * HID_ + n0 + tx];
    __syncthreads();
#pragma unroll
    for (int i = 0; i < 4; i++) {
        int r = ty + i * 8;
        float v = t[tx][r];
        size_t o = (size_t)(n0 + r) * KTOT + k0 + tx;
        __nv_bfloat16 hi = __float2bfloat16_rn(v);
        g_wt_hi[o] = hi;
        g_wt_lo[o] = __float2bfloat16_rn(v - __bfloat162float(hi));
    }
}

// ---------------- split-bf16 mma.sync GEMM, TMA-fed, BM=256 ----------------
__global__ void __launch_bounds__(256, 1)
gemm_kernel(const __grid_constant__ CUtensorMap tm_ah,
            const __grid_constant__ CUtensorMap tm_al,
            const __grid_constant__ CUtensorMap tm_bh,
            const __grid_constant__ CUtensorMap tm_bl,
            const float* __restrict__ W1, const float* __restrict__ b1,
            const float* __restrict__ W2, const int* __restrict__ count)
{
    extern __shared__ char smem[];
    const uint32_t sb = smem_to_u32(smem);
    const uint32_t db = (sb + 1023u) & ~1023u;          // data base, 1KB aligned
    const uint32_t mb = db + DATA_BYTES;                // 2 mbarriers
    const int tid = threadIdx.x, lane = tid & 31, wid = tid >> 5;
    const int wm = wid >> 1, wn = wid & 1;              // 4 x 2 warp grid, 64x64 tiles
    const int m0 = blockIdx.y * BM, n0 = blockIdx.x * BN;

    if (tid == 0) {
#pragma unroll
        for (int s = 0; s < STAGES; s++) MBAR_INIT(mb + s * 8, 1);
        FENCE_ASYNC();
    }
    __syncthreads();

    if (tid == 0) {
#pragma unroll
        for (int s = 0; s < STAGES; s++) {
            uint32_t st = db + s * STG_BYTES;
            MBAR_EXPECT(mb + s * 8, STG_BYTES);
            TMA_2D(st + A_HI, &tm_ah, s * BK, m0, mb + s * 8);
            TMA_2D(st + A_LO, &tm_al, s * BK, m0, mb + s * 8);
            TMA_2D(st + B_HI, &tm_bh, s * BK, n0, mb + s * 8);
            TMA_2D(st + B_LO, &tm_bl, s * BK, n0, mb + s * 8);
        }
    }

    float acc[4][8][4];
#pragma unroll
    for (int a = 0; a < 4; a++)
#pragma unroll
        for (int b = 0; b < 8; b++)
#pragma unroll
            for (int c = 0; c < 4; c++) acc[a][b][c] = 0.0f;

    int s = 0, phase = 0;
    for (int kt = 0; kt < KITER; kt++) {
        MBAR_WAIT(mb + s * 8, phase);
        const uint32_t stg = db + s * STG_BYTES;

#pragma unroll
        for (int ks = 0; ks < 4; ks++) {
            uint32_t ah[4][4], al[4][4], bh[8][2], bl[8][2];
            const int cb = ks * 2 + (lane >> 4);
#pragma unroll
            for (int mi = 0; mi < 4; mi++) {
                int row = wm * 64 + mi * 16 + (lane & 15);
                uint32_t off = swz(row, cb);
                ldsm4(ah[mi], stg + A_HI + off);
                ldsm4(al[mi], stg + A_LO + off);
            }
#pragma unroll
            for (int nj = 0; nj < 4; nj++) {
                int row = wn * 64 + nj * 16 + (lane & 15);
                uint32_t off = swz(row, cb);
                uint32_t t[4];
                ldsm4(t, stg + B_HI + off);
                bh[nj*2][0] = t[0]; bh[nj*2][1] = t[2];
                bh[nj*2+1][0] = t[1]; bh[nj*2+1][1] = t[3];
                ldsm4(t, stg + B_LO + off);
                bl[nj*2][0] = t[0]; bl[nj*2][1] = t[2];
                bl[nj*2+1][0] = t[1]; bl[nj*2+1][1] = t[3];
            }

            if (ks == 3) {
                // all LDSM reads of this stage are done -> refill overlaps mma
                __syncthreads();
                if (tid == 0 && kt + STAGES < KITER) {
                    int kn = kt + STAGES;
                    uint32_t st = db + s * STG_BYTES;
                    MBAR_EXPECT(mb + s * 8, STG_BYTES);
                    TMA_2D(st + A_HI, &tm_ah, kn * BK, m0, mb + s * 8);
                    TMA_2D(st + A_LO, &tm_al, kn * BK, m0, mb + s * 8);
                    TMA_2D(st + B_HI, &tm_bh, kn * BK, n0, mb + s * 8);
                    TMA_2D(st + B_LO, &tm_bl, kn * BK, n0, mb + s * 8);
                }
            }
#pragma unroll
            for (int mi = 0; mi < 4; mi++)
#pragma unroll
                for (int ni = 0; ni < 8; ni++) {
                    mma_bf16(acc[mi][ni], ah[mi], bh[ni]);
                    mma_bf16(acc[mi][ni], ah[mi], bl[ni]);
                    mma_bf16(acc[mi][ni], al[mi], bh[ni]);
                }
        }
        if (++s == STAGES) { s = 0; phase ^= 1; }
    }

    // ---- fused epilogue: z = acc + b1 + lc*W1[8320]; gelu(z)*W2 row-reduce ----
    const int r = lane >> 2, c2 = (lane & 3) * 2;
    const float* wl = W1 + (size_t)8320 * HID_;
    float pA[4], pB[4], lcA[4], lcB[4];
#pragma unroll
    for (int mi = 0; mi < 4; mi++) {
        int rowA = m0 + wm * 64 + mi * 16 + r;
        lcA[mi] = log1pf((float)count[rowA]);
        lcB[mi] = log1pf((float)count[rowA + 8]);
        pA[mi] = 0.0f; pB[mi] = 0.0f;
    }
#pragma unroll
    for (int ni = 0; ni < 8; ni++) {
        int n = n0 + wn * 64 + ni * 8 + c2;
        float b10 = b1[n], b11 = b1[n + 1];
        float wl0 = wl[n], wl1 = wl[n + 1];
        float w20 = W2[n], w21 = W2[n + 1];
#pragma unroll
        for (int mi = 0; mi < 4; mi++) {
            pA[mi] += gelu_exact(acc[mi][ni][0] + b10 + lcA[mi] * wl0) * w20
                    + gelu_exact(acc[mi][ni][1] + b11 + lcA[mi] * wl1) * w21;
            pB[mi] += gelu_exact(acc[mi][ni][2] + b10 + lcB[mi] * wl0) * w20
                    + gelu_exact(acc[mi][ni][3] + b11 + lcB[mi] * wl1) * w21;
        }
    }
#pragma unroll
    for (int mi = 0; mi < 4; mi++) {
        pA[mi] += __shfl_xor_sync(0xffffffffu, pA[mi], 1);
        pA[mi] += __shfl_xor_sync(0xffffffffu, pA[mi], 2);
        pB[mi] += __shfl_xor_sync(0xffffffffu, pB[mi], 1);
        pB[mi] += __shfl_xor_sync(0xffffffffu, pB[mi], 2);
    }
    __syncthreads();
    float* red = (float*)smem;          // reuse pipeline smem: [256 rows][2 wn]
    if ((lane & 3) == 0) {
#pragma unroll
        for (int mi = 0; mi < 4; mi++) {
            int rA = wm * 64 + mi * 16 + r;
            red[rA * 2 + wn]       = pA[mi];
            red[(rA + 8) * 2 + wn] = pB[mi];
        }
    }
    __syncthreads();
    {
        float sum = red[tid * 2] + red[tid * 2 + 1];
        g_part2[(size_t)blockIdx.x * N_ + m0 + tid] = sum;
    }
}

__global__ void final_kernel(const float* __restrict__ b2, float* __restrict__ out) {
    int i = blockIdx.x * 256 + threadIdx.x;
    float s = b2[0];
#pragma unroll
    for (int nb = 0; nb < 8; nb++) s += g_part2[(size_t)nb * N_ + i];
    out[i] = s;
}

// ---------------- host ----------------
typedef CUresult (CUDAAPI *EncodeFn)(
    CUtensorMap*, CUtensorMapDataType, cuuint32_t, void*,
    const cuuint64_t*, const cuuint64_t*, const cuuint32_t*, const cuuint32_t*,
    CUtensorMapInterleave, CUtensorMapSwizzle, CUtensorMapL2promotion, CUtensorMapFloatOOBfill);

static void encode2d(EncodeFn enc, CUtensorMap* m, void* ptr, uint64_t d0, uint64_t d1,
                     uint32_t rows) {
    cuuint64_t dims[2] = {d0, d1};
    cuuint64_t strides[1] = {d0 * 2};
    cuuint32_t box[2] = {64u, rows};   // 128B x rows, SW128
    cuuint32_t es[2] = {1u, 1u};
    enc(m, CU_TENSOR_MAP_DATA_TYPE_BFLOAT16, 2, ptr, dims, strides, box, es,
        CU_TENSOR_MAP_INTERLEAVE_NONE, CU_TENSOR_MAP_SWIZZLE_128B,
        CU_TENSOR_MAP_L2_PROMOTION_L2_128B, CU_TENSOR_MAP_FLOAT_OOB_FILL_NONE);
}

extern "C" void kernel_launch(void* const* d_in, const int* in_sizes, int n_in,
                              void* d_out, int out_size) {
    const float* q     = (const float*)d_in[0];
    const float* k     = (const float*)d_in[1];
    const int*   bidx  = (const int*)d_in[2];
    const void*  mask  = d_in[3];
    const int*   count = (const int*)d_in[4];
    const float* W1    = (const float*)d_in[5];
    const float* b1    = (const float*)d_in[6];
    const float* W2    = (const float*)d_in[7];
    const float* b2    = (const float*)d_in[8];
    float* out = (float*)d_out;

    void* encp = nullptr;
    cudaDriverEntryPointQueryResult st;
    cudaGetDriverEntryPointByVersion("cuTensorMapEncodeTiled", &encp, 12000,
                                     cudaEnableDefault, &st);
    EncodeFn enc = (EncodeFn)encp;

    void *p_fh, *p_fl, *p_wh, *p_wl;
    cudaGetSymbolAddress(&p_fh, g_feat_hi);
    cudaGetSymbolAddress(&p_fl, g_feat_lo);
    cudaGetSymbolAddress(&p_wh, g_wt_hi);
    cudaGetSymbolAddress(&p_wl, g_wt_lo);

    CUtensorMap tm_ah, tm_al, tm_bh, tm_bl;
    encode2d(enc, &tm_ah, p_fh, KTOT, N_, 256u);
    encode2d(enc, &tm_al, p_fl, KTOT, N_, 256u);
    encode2d(enc, &tm_bh, p_wh, KTOT, HID_, 128u);
    encode2d(enc, &tm_bl, p_wl, KTOT, HID_, 128u);

    cudaFuncSetAttribute(gemm_kernel, cudaFuncAttributeMaxDynamicSharedMemorySize, SMEM_ALLOC);

    detect_mask_kernel<<<1, 32>>>((const unsigned int*)mask);
    gather_idx_kernel<<<N_ / 8, 256>>>(mask);
    convert_feat_kernel<<<N_, 256>>>(q, k, bidx);
    convert_w1_kernel<<<dim3(KTOT / 32, HID_ / 32), dim3(32, 8)>>>(W1);
    gemm_kernel<<<dim3(HID_ / BN, N_ / BM), 256, SMEM_ALLOC>>>(tm_ah, tm_al, tm_bh, tm_bl,
                                                               W1, b1, W2, count);
    final_kernel<<<N_ / 256, 256>>>(b2, out);
}